// round 5
// baseline (speedup 1.0000x reference)
#include <cuda_runtime.h>

// Integrate-and-fire, hard reset, scanned over time axis.
// x: [T=32, N] float32, out: [T=32, N] float32 (spikes 0/1).
// N = 4,194,304 neurons. Each thread owns 8 neurons (2x float4 lanes,
// coalesced: lane A = base+tid, lane B = base+tid+blockDim), carries
// membrane potentials in registers, software-pipelines the loads so
// t+1's LDGs are in flight while t's chain + stores drain.

#define T_STEPS 32
#define V_TH 1.0f

__global__ __launch_bounds__(256) void if_scan_kernel(
    const float4* __restrict__ x,
    float4* __restrict__ out,
    int n4)
{
    int base = blockIdx.x * (blockDim.x * 2) + threadIdx.x;
    int ia = base;
    int ib = base + blockDim.x;
    if (ib >= n4) {
        // tail path (never taken for this shape, kept for safety)
        if (ia >= n4) return;
        float m0 = 0.f, m1 = 0.f, m2 = 0.f, m3 = 0.f;
        #pragma unroll
        for (int t = 0; t < T_STEPS; t++) {
            size_t idx = (size_t)t * n4 + ia;
            float4 xt = __ldcs(&x[idx]);
            m0 += xt.x; m1 += xt.y; m2 += xt.z; m3 += xt.w;
            float4 s;
            s.x = (m0 >= V_TH) ? 1.0f : 0.0f;
            s.y = (m1 >= V_TH) ? 1.0f : 0.0f;
            s.z = (m2 >= V_TH) ? 1.0f : 0.0f;
            s.w = (m3 >= V_TH) ? 1.0f : 0.0f;
            m0 = (s.x != 0.f) ? 0.f : m0;
            m1 = (s.y != 0.f) ? 0.f : m1;
            m2 = (s.z != 0.f) ? 0.f : m2;
            m3 = (s.w != 0.f) ? 0.f : m3;
            __stcs(&out[idx], s);
        }
        return;
    }

    // membrane state: 8 neurons
    float a0 = 0.f, a1 = 0.f, a2 = 0.f, a3 = 0.f;
    float b0 = 0.f, b1 = 0.f, b2 = 0.f, b3 = 0.f;

    // prologue: prefetch t=0
    float4 xa = __ldcs(&x[(size_t)ia]);
    float4 xb = __ldcs(&x[(size_t)ib]);

    #pragma unroll
    for (int t = 0; t < T_STEPS; t++) {
        float4 na, nb;
        if (t + 1 < T_STEPS) {
            size_t nidx = (size_t)(t + 1) * n4;
            na = __ldcs(&x[nidx + ia]);
            nb = __ldcs(&x[nidx + ib]);
        }

        a0 += xa.x; a1 += xa.y; a2 += xa.z; a3 += xa.w;
        b0 += xb.x; b1 += xb.y; b2 += xb.z; b3 += xb.w;

        float4 sa, sb;
        sa.x = (a0 >= V_TH) ? 1.0f : 0.0f;
        sa.y = (a1 >= V_TH) ? 1.0f : 0.0f;
        sa.z = (a2 >= V_TH) ? 1.0f : 0.0f;
        sa.w = (a3 >= V_TH) ? 1.0f : 0.0f;
        sb.x = (b0 >= V_TH) ? 1.0f : 0.0f;
        sb.y = (b1 >= V_TH) ? 1.0f : 0.0f;
        sb.z = (b2 >= V_TH) ? 1.0f : 0.0f;
        sb.w = (b3 >= V_TH) ? 1.0f : 0.0f;

        a0 = (sa.x != 0.f) ? 0.f : a0;
        a1 = (sa.y != 0.f) ? 0.f : a1;
        a2 = (sa.z != 0.f) ? 0.f : a2;
        a3 = (sa.w != 0.f) ? 0.f : a3;
        b0 = (sb.x != 0.f) ? 0.f : b0;
        b1 = (sb.y != 0.f) ? 0.f : b1;
        b2 = (sb.z != 0.f) ? 0.f : b2;
        b3 = (sb.w != 0.f) ? 0.f : b3;

        size_t oidx = (size_t)t * n4;
        __stcs(&out[oidx + ia], sa);
        __stcs(&out[oidx + ib], sb);

        xa = na;
        xb = nb;
    }
}

extern "C" void kernel_launch(void* const* d_in, const int* in_sizes, int n_in,
                              void* d_out, int out_size)
{
    const float* x = (const float*)d_in[0];
    float* out = (float*)d_out;

    int total = in_sizes[0];          // T * N
    int n = total / T_STEPS;          // neurons
    int n4 = n / 4;                   // float4 lanes

    int threads = 256;
    int lanes_per_block = threads * 2;
    int blocks = (n4 + lanes_per_block - 1) / lanes_per_block;

    if_scan_kernel<<<blocks, threads>>>(
        (const float4*)x, (float4*)out, n4);
}

// round 6
// speedup vs baseline: 1.0098x; 1.0098x over previous
#include <cuda_runtime.h>

// Integrate-and-fire, hard reset, scanned over time axis.
// x: [T=32, N] float32, out: [T=32, N] float32 (spikes 0/1).
// N = 4,194,304 neurons. Each thread owns 8 consecutive neurons and uses
// Blackwell 256-bit global loads/stores (ld.global.nc.v8 / st.global.v8).
// Membrane potentials carried in registers across the fully unrolled T loop.

#define T_STEPS 32
#define V_TH 1.0f

__device__ __forceinline__ void ldg256(const float* p, float r[8]) {
    asm volatile(
        "ld.global.nc.v8.f32 {%0,%1,%2,%3,%4,%5,%6,%7}, [%8];"
        : "=f"(r[0]), "=f"(r[1]), "=f"(r[2]), "=f"(r[3]),
          "=f"(r[4]), "=f"(r[5]), "=f"(r[6]), "=f"(r[7])
        : "l"(p));
}

__device__ __forceinline__ void stg256(float* p, const float r[8]) {
    asm volatile(
        "st.global.v8.f32 [%0], {%1,%2,%3,%4,%5,%6,%7,%8};"
        :: "l"(p),
           "f"(r[0]), "f"(r[1]), "f"(r[2]), "f"(r[3]),
           "f"(r[4]), "f"(r[5]), "f"(r[6]), "f"(r[7])
        : "memory");
}

__global__ __launch_bounds__(256) void if_scan_kernel(
    const float* __restrict__ x,
    float* __restrict__ out,
    int n8)   // number of 8-float lanes per timestep
{
    int i = blockIdx.x * blockDim.x + threadIdx.x;
    if (i >= n8) return;

    size_t elem = (size_t)i * 8;   // float offset within a timestep slice
    size_t stride = (size_t)n8 * 8; // floats per timestep

    float m[8];
    #pragma unroll
    for (int k = 0; k < 8; k++) m[k] = 0.0f;

    #pragma unroll
    for (int t = 0; t < T_STEPS; t++) {
        size_t idx = (size_t)t * stride + elem;
        float xt[8];
        ldg256(x + idx, xt);

        float s[8];
        #pragma unroll
        for (int k = 0; k < 8; k++) {
            m[k] += xt[k];
            s[k] = (m[k] >= V_TH) ? 1.0f : 0.0f;
            m[k] = (s[k] != 0.0f) ? 0.0f : m[k];
        }

        stg256(out + idx, s);
    }
}

extern "C" void kernel_launch(void* const* d_in, const int* in_sizes, int n_in,
                              void* d_out, int out_size)
{
    const float* x = (const float*)d_in[0];
    float* out = (float*)d_out;

    int total = in_sizes[0];          // T * N
    int n = total / T_STEPS;          // neurons per timestep
    int n8 = n / 8;                   // 8-float lanes

    int threads = 256;
    int blocks = (n8 + threads - 1) / threads;

    if_scan_kernel<<<blocks, threads>>>(x, out, n8);
}